// round 1
// baseline (speedup 1.0000x reference)
#include <cuda_runtime.h>

// Problem constants (fixed by the dataset)
#define BB 4
#define NN 4096
#define KK 32
#define CC 64
#define FD 128          // fuse dim = D1 + D2
#define DHH 128
#define BN (BB * NN)

// Scratch (no cudaMalloc allowed) — 24 MB total
__device__ float g_ctr[(size_t)BN * FD];     // [U1 ; Gv] per point
__device__ float g_nbr[(size_t)BN * FD];     // [U2 ; Gv] per point
__device__ float g_pooled[(size_t)BN * DHH];

// ---------------------------------------------------------------------------
// Kernel 1: precompute U1/U2 (from xyz through W_gu split 3+3) and Gv = W_gv@feat
// ---------------------------------------------------------------------------
__global__ void __launch_bounds__(128) precompute_kernel(
    const float* __restrict__ xyz,       // (B,N,3)
    const float* __restrict__ features,  // (B,C,N)
    const float* __restrict__ W_gu,      // (64,6)
    const float* __restrict__ W_gv)      // (64,64)
{
    __shared__ float sWgv[64 * 64];  // transposed: sWgv[c*64+o] = W_gv[o*64+c]
    __shared__ float sWgu[64 * 6];
    __shared__ float sfeat[64];
    __shared__ float sxyz[3];
    int t = threadIdx.x;

    for (int e = t; e < 64 * 64; e += 128)
        sWgv[(e & 63) * 64 + (e >> 6)] = W_gv[e];
    for (int e = t; e < 64 * 6; e += 128)
        sWgu[e] = W_gu[e];

    for (int p = blockIdx.x; p < BN; p += gridDim.x) {
        int b = p >> 12;
        int n = p & (NN - 1);
        __syncthreads();  // protect sfeat/sxyz reuse
        if (t < 64)
            sfeat[t] = features[(size_t)b * CC * NN + (size_t)t * NN + n];
        if (t >= 64 && t < 67)
            sxyz[t - 64] = xyz[(size_t)p * 3 + (t - 64)];
        __syncthreads();

        if (t < 64) {
            int o = t;
            float x0 = sxyz[0], x1 = sxyz[1], x2 = sxyz[2];
            float u1 = sWgu[o * 6 + 0] * x0 + sWgu[o * 6 + 1] * x1 + sWgu[o * 6 + 2] * x2;
            float u2 = sWgu[o * 6 + 3] * x0 + sWgu[o * 6 + 4] * x1 + sWgu[o * 6 + 5] * x2;
            g_ctr[(size_t)p * FD + o] = u1;
            g_nbr[(size_t)p * FD + o] = u2;
        } else {
            int o = t - 64;
            float acc = 0.f;
#pragma unroll
            for (int c = 0; c < 64; c++)
                acc += sWgv[c * 64 + o] * sfeat[c];
            g_ctr[(size_t)p * FD + 64 + o] = acc;
            g_nbr[(size_t)p * FD + 64 + o] = acc;
        }
    }
}

// ---------------------------------------------------------------------------
// Kernel 2: main — per point: gather+ReLU fuse (16 nbrs/batch), 16x128x128 GEMM
// with W_h in smem, ReLU + K-mean pooling.
// Block: 128 threads; thread (qb = t>>5, ob = t&31) owns a 4x4 (q,o) tile.
// ---------------------------------------------------------------------------
#define SW_STRIDE 132                       // 132*4 bytes: float4-aligned, conflict-free
#define SM_W_FLOATS (128 * SW_STRIDE)       // 16896
#define SM_FUSE_FLOATS (16 * 128)           // 2048
#define SM_RED_FLOATS (4 * 128)             // 512
#define MAIN_SMEM_BYTES ((SM_W_FLOATS + SM_FUSE_FLOATS + SM_RED_FLOATS) * 4)  // 77824

__global__ void __launch_bounds__(128) main_kernel(
    const int* __restrict__ idx,   // (N,K)
    const float* __restrict__ s_gu, const float* __restrict__ b_gu,
    const float* __restrict__ s_gv, const float* __restrict__ b_gv,
    const float* __restrict__ W_h,  // (128,128)
    const float* __restrict__ s_h, const float* __restrict__ b_h)
{
    extern __shared__ float sm[];
    float* sW = sm;                          // sW[i*132 + o] = W_h[o*128 + i]
    float* sFuse = sm + SM_W_FLOATS;         // sFuse[q*128 + i]
    float* sRed = sFuse + SM_FUSE_FLOATS;    // sRed[qb*128 + o]

    int t = threadIdx.x;
    int qb = t >> 5;
    int ob = t & 31;

    // load + transpose W_h (coalesced LDG, 4-way STS conflicts, one-time)
    for (int e = t; e < 128 * 128; e += 128)
        sW[(e & 127) * SW_STRIDE + (e >> 7)] = W_h[e];

    // per-thread fuse scale/bias (feature index == t)
    float sv = (t < 64) ? s_gu[t] : s_gv[t - 64];
    float bv = (t < 64) ? b_gu[t] : b_gv[t - 64];
    float sh[4], bh[4];
#pragma unroll
    for (int oo = 0; oo < 4; oo++) {
        sh[oo] = s_h[ob * 4 + oo];
        bh[oo] = b_h[ob * 4 + oo];
    }
    __syncthreads();

    for (int p = blockIdx.x; p < BN; p += gridDim.x) {
        int b = p >> 12;
        int n = p & (NN - 1);
        float ctr = g_ctr[(size_t)p * FD + t];
        const float* nb = g_nbr + (size_t)b * NN * FD;
        const int* ip = idx + n * KK;
        float pool[4] = {0.f, 0.f, 0.f, 0.f};

#pragma unroll
        for (int batch = 0; batch < 2; batch++) {
            __syncthreads();  // previous consumers of sFuse (and sRed) done
            // gather + ReLU: thread t fills feature column t for 16 neighbors
#pragma unroll
            for (int q = 0; q < 16; q++) {
                int j = ip[batch * 16 + q];
                float v = nb[(size_t)j * FD + t];
                sFuse[q * 128 + t] = fmaxf((ctr + v) * sv + bv, 0.f);
            }
            __syncthreads();

            float acc[4][4];
#pragma unroll
            for (int a = 0; a < 4; a++)
#pragma unroll
                for (int c = 0; c < 4; c++) acc[a][c] = 0.f;

#pragma unroll 16
            for (int i = 0; i < 128; i++) {
                float4 w = *(const float4*)&sW[i * SW_STRIDE + (ob << 2)];
                float a0 = sFuse[(qb * 4 + 0) * 128 + i];
                float a1 = sFuse[(qb * 4 + 1) * 128 + i];
                float a2 = sFuse[(qb * 4 + 2) * 128 + i];
                float a3 = sFuse[(qb * 4 + 3) * 128 + i];
                acc[0][0] += a0 * w.x; acc[0][1] += a0 * w.y; acc[0][2] += a0 * w.z; acc[0][3] += a0 * w.w;
                acc[1][0] += a1 * w.x; acc[1][1] += a1 * w.y; acc[1][2] += a1 * w.z; acc[1][3] += a1 * w.w;
                acc[2][0] += a2 * w.x; acc[2][1] += a2 * w.y; acc[2][2] += a2 * w.z; acc[2][3] += a2 * w.w;
                acc[3][0] += a3 * w.x; acc[3][1] += a3 * w.y; acc[3][2] += a3 * w.z; acc[3][3] += a3 * w.w;
            }

#pragma unroll
            for (int qq = 0; qq < 4; qq++)
#pragma unroll
                for (int oo = 0; oo < 4; oo++)
                    pool[oo] += fmaxf(acc[qq][oo] * sh[oo] + bh[oo], 0.f);
        }

        // cross-qb reduction of pooled h, then mean over K=32
        *(float4*)&sRed[qb * 128 + (ob << 2)] =
            make_float4(pool[0], pool[1], pool[2], pool[3]);
        __syncthreads();
        float ps = (sRed[t] + sRed[128 + t] + sRed[256 + t] + sRed[384 + t]) * (1.0f / KK);
        g_pooled[(size_t)p * DHH + t] = ps;
    }
}

// ---------------------------------------------------------------------------
// Kernel 3: epilogue — out[b,c,n] = relu((W_f @ pooled)*s_f + b_f) + features
// ---------------------------------------------------------------------------
__global__ void __launch_bounds__(128) epilogue_kernel(
    const float* __restrict__ W_f,  // (64,128)
    const float* __restrict__ s_f, const float* __restrict__ b_f,
    const float* __restrict__ features,
    float* __restrict__ out)
{
    __shared__ float sWf[128 * 65];  // sWf[i*65 + c] = W_f[c*128 + i]
    __shared__ float sPool[128];
    int t = threadIdx.x;

    for (int e = t; e < 64 * 128; e += 128)
        sWf[(e & 127) * 65 + (e >> 7)] = W_f[e];

    for (int p = blockIdx.x; p < BN; p += gridDim.x) {
        __syncthreads();
        sPool[t] = g_pooled[(size_t)p * DHH + t];
        __syncthreads();
        if (t < 64) {
            float acc = 0.f;
#pragma unroll 16
            for (int i = 0; i < 128; i++)
                acc += sWf[i * 65 + t] * sPool[i];
            int b = p >> 12;
            int n = p & (NN - 1);
            size_t o = (size_t)b * CC * NN + (size_t)t * NN + n;
            out[o] = fmaxf(acc * s_f[t] + b_f[t], 0.f) + features[o];
        }
    }
}

// ---------------------------------------------------------------------------
extern "C" void kernel_launch(void* const* d_in, const int* in_sizes, int n_in,
                              void* d_out, int out_size)
{
    const float* xyz      = (const float*)d_in[0];
    const float* features = (const float*)d_in[1];
    const int*   idx      = (const int*)d_in[2];
    const float* W_gu     = (const float*)d_in[3];
    const float* s_gu     = (const float*)d_in[4];
    const float* b_gu     = (const float*)d_in[5];
    const float* W_gv     = (const float*)d_in[6];
    const float* s_gv     = (const float*)d_in[7];
    const float* b_gv     = (const float*)d_in[8];
    const float* W_h      = (const float*)d_in[9];
    const float* s_h      = (const float*)d_in[10];
    const float* b_h      = (const float*)d_in[11];
    const float* W_f      = (const float*)d_in[12];
    const float* s_f      = (const float*)d_in[13];
    const float* b_f      = (const float*)d_in[14];

    float* out = (float*)d_out;
    float* out_feat = out;
    const size_t xyz_elems = (size_t)BB * NN * 3;
    const size_t feat_elems = (size_t)BB * CC * NN;

    // Reference returns (xyz, out): if the output buffer holds both, copy the
    // xyz passthrough up front and write features after it.
    if ((size_t)out_size == xyz_elems + feat_elems) {
        cudaMemcpyAsync(out, xyz, xyz_elems * sizeof(float),
                        cudaMemcpyDeviceToDevice, 0);
        out_feat = out + xyz_elems;
    }

    cudaFuncSetAttribute(main_kernel,
                         cudaFuncAttributeMaxDynamicSharedMemorySize,
                         MAIN_SMEM_BYTES);

    precompute_kernel<<<2048, 128>>>(xyz, features, W_gu, W_gv);
    main_kernel<<<1024, 128, MAIN_SMEM_BYTES>>>(idx, s_gu, b_gu, s_gv, b_gv,
                                                W_h, s_h, b_h);
    epilogue_kernel<<<512, 128>>>(W_f, s_f, b_f, features, out_feat);
}

// round 2
// speedup vs baseline: 1.0447x; 1.0447x over previous
#include <cuda_runtime.h>

// Problem constants (fixed by the dataset)
#define BB 4
#define NN 4096
#define KK 32
#define CC 64
#define FD 128          // fuse dim = D1 + D2
#define DHH 128
#define BN (BB * NN)

// Scratch (no cudaMalloc allowed) — 24 MB total
__device__ float g_ctr[(size_t)BN * FD];     // [U1 ; Gv] per point
__device__ float g_nbr[(size_t)BN * FD];     // [U2 ; Gv] per point
__device__ float g_pooled[(size_t)BN * DHH];

// Packed f32x2 helpers (FFMA2 is only reachable via PTX on sm_103a)
#define PACK2(d, lo, hi)  asm("mov.b64 %0, {%1,%2};" : "=l"(d) : "f"(lo), "f"(hi))
#define UNPACK2(lo, hi, s) asm("mov.b64 {%0,%1}, %2;" : "=f"(lo), "=f"(hi) : "l"(s))
#define FFMA2(d, a, b)    asm("fma.rn.f32x2 %0, %1, %2, %0;" : "+l"(d) : "l"(a), "l"(b))

// ---------------------------------------------------------------------------
// Kernel 1: precompute. Per block: 32 consecutive points.
//   g_ctr[p] = [U1(xyz_p) ; Gv(feat_p)],  g_nbr[p] = [U2(xyz_p) ; Gv(feat_p)]
// ---------------------------------------------------------------------------
__global__ void __launch_bounds__(128) precompute_kernel(
    const float* __restrict__ xyz,       // (B,N,3)
    const float* __restrict__ features,  // (B,C,N)
    const float* __restrict__ W_gu,      // (64,6)
    const float* __restrict__ W_gv)      // (64,64)
{
    __shared__ float sWgv[64 * 64];      // [c][o]
    __shared__ float sWgu[64 * 6];
    __shared__ float sF[64 * 33];        // [c][np], pad 33
    __shared__ float sXyz[32 * 3];
    __shared__ float sOut[32 * 132];     // [np][f], pad 132

    int t = threadIdx.x;
    int p0 = blockIdx.x * 32;
    int b = p0 >> 12;
    int n0 = p0 & (NN - 1);

    for (int e = t; e < 64 * 64; e += 128)
        sWgv[(e & 63) * 64 + (e >> 6)] = W_gv[e];   // transpose: [c][o]
    for (int e = t; e < 64 * 6; e += 128)
        sWgu[e] = W_gu[e];
    for (int e = t; e < 64 * 32; e += 128) {
        int c = e >> 5, np = e & 31;
        sF[c * 33 + np] = features[(size_t)b * CC * NN + (size_t)c * NN + n0 + np];
    }
    for (int e = t; e < 96; e += 128)
        sXyz[e] = xyz[(size_t)p0 * 3 + e];
    __syncthreads();

    // Gv: thread (np = t&31, o0 = (t>>5)*16) computes 16 outputs
    {
        int np = t & 31;
        int o0 = (t >> 5) << 4;
        float acc[16];
#pragma unroll
        for (int j = 0; j < 16; j++) acc[j] = 0.f;
#pragma unroll 8
        for (int c = 0; c < 64; c++) {
            float a = sF[c * 33 + np];
            const float4* wp = (const float4*)&sWgv[c * 64 + o0];
#pragma unroll
            for (int v = 0; v < 4; v++) {
                float4 w = wp[v];
                acc[v * 4 + 0] += a * w.x;
                acc[v * 4 + 1] += a * w.y;
                acc[v * 4 + 2] += a * w.z;
                acc[v * 4 + 3] += a * w.w;
            }
        }
#pragma unroll
        for (int j = 0; j < 16; j++)
            sOut[np * 132 + 64 + o0 + j] = acc[j];
    }
    // U1 into sOut[:, 0:64]
    for (int e = t; e < 32 * 64; e += 128) {
        int np = e >> 6, o = e & 63;
        float x0 = sXyz[np * 3], x1 = sXyz[np * 3 + 1], x2 = sXyz[np * 3 + 2];
        sOut[np * 132 + o] = sWgu[o * 6 + 0] * x0 + sWgu[o * 6 + 1] * x1 + sWgu[o * 6 + 2] * x2;
    }
    __syncthreads();
    // write g_ctr (coalesced float4)
    for (int e = t * 4; e < 32 * 128; e += 512) {
        int np = e >> 7, f = e & 127;
        *(float4*)&g_ctr[(size_t)p0 * FD + e] = *(const float4*)&sOut[np * 132 + f];
    }
    __syncthreads();
    // overwrite first 64 cols with U2, write g_nbr
    for (int e = t; e < 32 * 64; e += 128) {
        int np = e >> 6, o = e & 63;
        float x0 = sXyz[np * 3], x1 = sXyz[np * 3 + 1], x2 = sXyz[np * 3 + 2];
        sOut[np * 132 + o] = sWgu[o * 6 + 3] * x0 + sWgu[o * 6 + 4] * x1 + sWgu[o * 6 + 5] * x2;
    }
    __syncthreads();
    for (int e = t * 4; e < 32 * 128; e += 512) {
        int np = e >> 7, f = e & 127;
        *(float4*)&g_nbr[(size_t)p0 * FD + e] = *(const float4*)&sOut[np * 132 + f];
    }
}

// ---------------------------------------------------------------------------
// Kernel 2: main. Per point: gather all 32 neighbors into duplicated-transposed
// fuse smem, then 32x128x128 GEMM with packed FFMA2, ReLU + K-mean pooling.
// Block 128 threads: thread (qb = t>>5 owns 8 q's, ob = t&31 owns 4 o's).
// ---------------------------------------------------------------------------
#define SW_STRIDE 132                        // conflict-free float4 reads
#define SFT_STRIDE 66                        // [i][q*2] duplicated pairs (even for LDS.64)
#define SM_W_FLOATS (128 * SW_STRIDE)        // 16896
#define SM_FT_FLOATS (128 * SFT_STRIDE)      // 8448
#define SM_RED_FLOATS (4 * 128)              // 512
#define MAIN_SMEM_BYTES ((SM_W_FLOATS + SM_FT_FLOATS + SM_RED_FLOATS) * 4)  // 103424

__global__ void __launch_bounds__(128) main_kernel(
    const int* __restrict__ idx,   // (N,K)
    const float* __restrict__ s_gu, const float* __restrict__ b_gu,
    const float* __restrict__ s_gv, const float* __restrict__ b_gv,
    const float* __restrict__ W_h,  // (128,128)
    const float* __restrict__ s_h, const float* __restrict__ b_h)
{
    extern __shared__ float sm[];
    float* sW = sm;                          // sW[i*132 + o] = W_h[o*128 + i]
    float* sFuseT = sm + SM_W_FLOATS;        // sFuseT[i*66 + q*2 + {0,1}] = fuse[q][i] (dup)
    float* sRed = sFuseT + SM_FT_FLOATS;     // sRed[qb*128 + o]

    int t = threadIdx.x;
    int qb = t >> 5;
    int ob = t & 31;

    for (int e = t; e < 128 * 128; e += 128)
        sW[(e & 127) * SW_STRIDE + (e >> 7)] = W_h[e];

    float sv = (t < 64) ? s_gu[t] : s_gv[t - 64];
    float bv = (t < 64) ? b_gu[t] : b_gv[t - 64];
    float sh[4], bh[4];
#pragma unroll
    for (int oo = 0; oo < 4; oo++) {
        sh[oo] = s_h[ob * 4 + oo];
        bh[oo] = b_h[ob * 4 + oo];
    }
    __syncthreads();

    for (int p = blockIdx.x; p < BN; p += gridDim.x) {
        int b = p >> 12;
        int n = p & (NN - 1);
        float ctr = g_ctr[(size_t)p * FD + t];
        const float* nb = g_nbr + (size_t)b * NN * FD;
        const int* ip = idx + n * KK;

        __syncthreads();  // prior readers of sFuseT / sRed done
        // gather + ReLU: thread t = feature i, all 32 neighbors, duplicated store
#pragma unroll 8
        for (int q = 0; q < KK; q++) {
            int j = __ldg(&ip[q]);
            float v = nb[(size_t)j * FD + t];
            float f = fmaxf((ctr + v) * sv + bv, 0.f);
            *(float2*)&sFuseT[t * SFT_STRIDE + q * 2] = make_float2(f, f);
        }
        __syncthreads();

        unsigned long long acc[8][2];
#pragma unroll
        for (int j = 0; j < 8; j++) { acc[j][0] = 0ull; acc[j][1] = 0ull; }

#pragma unroll 4
        for (int i = 0; i < 128; i++) {
            float4 w = *(const float4*)&sW[i * SW_STRIDE + (ob << 2)];
            unsigned long long w01, w23;
            PACK2(w01, w.x, w.y);
            PACK2(w23, w.z, w.w);
            const unsigned long long* ap =
                (const unsigned long long*)&sFuseT[i * SFT_STRIDE + (qb << 4)];
#pragma unroll
            for (int j = 0; j < 8; j++) {
                unsigned long long a = ap[j];   // LDS.64 broadcast: (fuse, fuse)
                FFMA2(acc[j][0], a, w01);
                FFMA2(acc[j][1], a, w23);
            }
        }

        float pool0 = 0.f, pool1 = 0.f, pool2 = 0.f, pool3 = 0.f;
#pragma unroll
        for (int j = 0; j < 8; j++) {
            float x, y, z, w;
            UNPACK2(x, y, acc[j][0]);
            UNPACK2(z, w, acc[j][1]);
            pool0 += fmaxf(x * sh[0] + bh[0], 0.f);
            pool1 += fmaxf(y * sh[1] + bh[1], 0.f);
            pool2 += fmaxf(z * sh[2] + bh[2], 0.f);
            pool3 += fmaxf(w * sh[3] + bh[3], 0.f);
        }

        *(float4*)&sRed[qb * 128 + (ob << 2)] = make_float4(pool0, pool1, pool2, pool3);
        __syncthreads();
        float ps = (sRed[t] + sRed[128 + t] + sRed[256 + t] + sRed[384 + t]) * (1.0f / KK);
        g_pooled[(size_t)p * DHH + t] = ps;
    }
}

// ---------------------------------------------------------------------------
// Kernel 3: epilogue. Per block: 32 points.
//   out[b,c,n] = relu((W_f @ pooled)*s_f + b_f) + features[b,c,n]
// ---------------------------------------------------------------------------
#define EPI_SWF (128 * 68)
#define EPI_SPOOL (32 * 129)
#define EPI_SOUT (64 * 33)
#define EPI_SMEM_BYTES ((EPI_SWF + EPI_SPOOL + EPI_SOUT) * 4)   // ~60 KB

__global__ void __launch_bounds__(128) epilogue_kernel(
    const float* __restrict__ W_f,  // (64,128)
    const float* __restrict__ s_f, const float* __restrict__ b_f,
    const float* __restrict__ features,
    float* __restrict__ out)
{
    extern __shared__ float sm[];
    float* sWf = sm;                  // sWf[i*68 + c] = W_f[c*128 + i]
    float* sPool = sWf + EPI_SWF;     // sPool[np*129 + i]
    float* sOutE = sPool + EPI_SPOOL; // sOutE[c*33 + np]

    int t = threadIdx.x;
    int p0 = blockIdx.x * 32;
    int b = p0 >> 12;
    int n0 = p0 & (NN - 1);

    for (int e = t; e < 64 * 128; e += 128) {
        int c = e >> 7, i = e & 127;
        sWf[i * 68 + c] = W_f[e];
    }
    for (int e = t; e < 32 * 128; e += 128) {
        int np = e >> 7, i = e & 127;
        sPool[np * 129 + i] = g_pooled[(size_t)p0 * DHH + e];
    }
    __syncthreads();

    // thread (np = t&31, c0 = (t>>5)*16) computes 16 channels for one point
    {
        int np = t & 31;
        int c0 = (t >> 5) << 4;
        float acc[16];
#pragma unroll
        for (int j = 0; j < 16; j++) acc[j] = 0.f;
#pragma unroll 8
        for (int i = 0; i < 128; i++) {
            float a = sPool[np * 129 + i];
            const float4* wp = (const float4*)&sWf[i * 68 + c0];
#pragma unroll
            for (int v = 0; v < 4; v++) {
                float4 w = wp[v];
                acc[v * 4 + 0] += a * w.x;
                acc[v * 4 + 1] += a * w.y;
                acc[v * 4 + 2] += a * w.z;
                acc[v * 4 + 3] += a * w.w;
            }
        }
#pragma unroll
        for (int j = 0; j < 16; j++) {
            int c = c0 + j;
            sOutE[c * 33 + np] = fmaxf(acc[j] * __ldg(&s_f[c]) + __ldg(&b_f[c]), 0.f);
        }
    }
    __syncthreads();

    for (int e = t; e < 64 * 32; e += 128) {
        int c = e >> 5, np = e & 31;
        size_t o = (size_t)b * CC * NN + (size_t)c * NN + n0 + np;
        out[o] = sOutE[c * 33 + np] + features[o];
    }
}

// ---------------------------------------------------------------------------
extern "C" void kernel_launch(void* const* d_in, const int* in_sizes, int n_in,
                              void* d_out, int out_size)
{
    const float* xyz      = (const float*)d_in[0];
    const float* features = (const float*)d_in[1];
    const int*   idx      = (const int*)d_in[2];
    const float* W_gu     = (const float*)d_in[3];
    const float* s_gu     = (const float*)d_in[4];
    const float* b_gu     = (const float*)d_in[5];
    const float* W_gv     = (const float*)d_in[6];
    const float* s_gv     = (const float*)d_in[7];
    const float* b_gv     = (const float*)d_in[8];
    const float* W_h      = (const float*)d_in[9];
    const float* s_h      = (const float*)d_in[10];
    const float* b_h      = (const float*)d_in[11];
    const float* W_f      = (const float*)d_in[12];
    const float* s_f      = (const float*)d_in[13];
    const float* b_f      = (const float*)d_in[14];

    float* out = (float*)d_out;
    float* out_feat = out;
    const size_t xyz_elems = (size_t)BB * NN * 3;
    const size_t feat_elems = (size_t)BB * CC * NN;

    if ((size_t)out_size == xyz_elems + feat_elems) {
        cudaMemcpyAsync(out, xyz, xyz_elems * sizeof(float),
                        cudaMemcpyDeviceToDevice, 0);
        out_feat = out + xyz_elems;
    }

    cudaFuncSetAttribute(main_kernel,
                         cudaFuncAttributeMaxDynamicSharedMemorySize,
                         MAIN_SMEM_BYTES);
    cudaFuncSetAttribute(epilogue_kernel,
                         cudaFuncAttributeMaxDynamicSharedMemorySize,
                         EPI_SMEM_BYTES);

    precompute_kernel<<<BN / 32, 128>>>(xyz, features, W_gu, W_gv);
    main_kernel<<<2048, 128, MAIN_SMEM_BYTES>>>(idx, s_gu, b_gu, s_gv, b_gv,
                                                W_h, s_h, b_h);
    epilogue_kernel<<<BN / 32, 128, EPI_SMEM_BYTES>>>(W_f, s_f, b_f, features,
                                                      out_feat);
}

// round 4
// speedup vs baseline: 1.9841x; 1.8992x over previous
#include <cuda_runtime.h>
#include <cstdint>

// Problem constants
#define BB 4
#define NN 4096
#define KK 32
#define CC 64
#define FD 128
#define DHH 128
#define BN (BB * NN)
#define NTILES (BN / 4)        // 4 points per tile (M = 4*32 = 128)

// Scratch (no cudaMalloc allowed)
__device__ float g_ctr[(size_t)BN * FD];
__device__ float g_nbr[(size_t)BN * FD];
__device__ float g_pooled[(size_t)BN * DHH];

// ---------------------------------------------------------------------------
// PTX helpers — baseline sm_80+ instructions only (compute_103-safe).
// ---------------------------------------------------------------------------
__device__ __forceinline__ uint32_t smem_u32(const void* p) {
    uint32_t a;
    asm("{ .reg .u64 t; cvta.to.shared.u64 t, %1; cvt.u32.u64 %0, t; }"
        : "=r"(a) : "l"(p));
    return a;
}

#define LDSM_X4(r0, r1, r2, r3, addr)                                        \
    asm volatile("ldmatrix.sync.aligned.m8n8.x4.shared.b16 {%0,%1,%2,%3}, [%4];" \
                 : "=r"(r0), "=r"(r1), "=r"(r2), "=r"(r3) : "r"(addr))

#define MMA_BF16(d, a, b0, b1)                                               \
    asm volatile("mma.sync.aligned.m16n8k16.row.col.f32.bf16.bf16.f32 "      \
                 "{%0,%1,%2,%3}, {%4,%5,%6,%7}, {%8,%9}, {%0,%1,%2,%3};"     \
                 : "+f"((d)[0]), "+f"((d)[1]), "+f"((d)[2]), "+f"((d)[3])    \
                 : "r"((a)[0]), "r"((a)[1]), "r"((a)[2]), "r"((a)[3]),       \
                   "r"(b0), "r"(b1))

// bf16 hi/lo split of an fp32 pair -> two packed bf16x2 words
__device__ __forceinline__ void split2(float f0, float f1, uint32_t& hi, uint32_t& lo) {
    asm("cvt.rn.satfinite.bf16x2.f32 %0, %1, %2;" : "=r"(hi) : "f"(f1), "f"(f0));
    float h0 = __uint_as_float(hi << 16);
    float h1 = __uint_as_float(hi & 0xffff0000u);
    asm("cvt.rn.satfinite.bf16x2.f32 %0, %1, %2;" : "=r"(lo) : "f"(f1 - h1), "f"(f0 - h0));
}

// ---------------------------------------------------------------------------
// Kernel 1: precompute  g_ctr[p]=[U1;Gv], g_nbr[p]=[U2;Gv]
// ---------------------------------------------------------------------------
__global__ void __launch_bounds__(128) precompute_kernel(
    const float* __restrict__ xyz, const float* __restrict__ features,
    const float* __restrict__ W_gu, const float* __restrict__ W_gv)
{
    __shared__ float sWgv[64 * 64];
    __shared__ float sWgu[64 * 6];
    __shared__ float sF[64 * 33];
    __shared__ float sXyz[32 * 3];
    __shared__ float sOut[32 * 132];

    int t = threadIdx.x;
    int p0 = blockIdx.x * 32;
    int b = p0 >> 12;
    int n0 = p0 & (NN - 1);

    for (int e = t; e < 64 * 64; e += 128)
        sWgv[(e & 63) * 64 + (e >> 6)] = W_gv[e];
    for (int e = t; e < 64 * 6; e += 128)
        sWgu[e] = W_gu[e];
    for (int e = t; e < 64 * 32; e += 128) {
        int c = e >> 5, np = e & 31;
        sF[c * 33 + np] = features[(size_t)b * CC * NN + (size_t)c * NN + n0 + np];
    }
    for (int e = t; e < 96; e += 128)
        sXyz[e] = xyz[(size_t)p0 * 3 + e];
    __syncthreads();

    {
        int np = t & 31;
        int o0 = (t >> 5) << 4;
        float acc[16];
#pragma unroll
        for (int j = 0; j < 16; j++) acc[j] = 0.f;
#pragma unroll 8
        for (int c = 0; c < 64; c++) {
            float a = sF[c * 33 + np];
            const float4* wp = (const float4*)&sWgv[c * 64 + o0];
#pragma unroll
            for (int v = 0; v < 4; v++) {
                float4 w = wp[v];
                acc[v * 4 + 0] += a * w.x;
                acc[v * 4 + 1] += a * w.y;
                acc[v * 4 + 2] += a * w.z;
                acc[v * 4 + 3] += a * w.w;
            }
        }
#pragma unroll
        for (int j = 0; j < 16; j++)
            sOut[np * 132 + 64 + o0 + j] = acc[j];
    }
    for (int e = t; e < 32 * 64; e += 128) {
        int np = e >> 6, o = e & 63;
        float x0 = sXyz[np * 3], x1 = sXyz[np * 3 + 1], x2 = sXyz[np * 3 + 2];
        sOut[np * 132 + o] = sWgu[o * 6 + 0] * x0 + sWgu[o * 6 + 1] * x1 + sWgu[o * 6 + 2] * x2;
    }
    __syncthreads();
    for (int e = t * 4; e < 32 * 128; e += 512) {
        int np = e >> 7, f = e & 127;
        *(float4*)&g_ctr[(size_t)p0 * FD + e] = *(const float4*)&sOut[np * 132 + f];
    }
    __syncthreads();
    for (int e = t; e < 32 * 64; e += 128) {
        int np = e >> 6, o = e & 63;
        float x0 = sXyz[np * 3], x1 = sXyz[np * 3 + 1], x2 = sXyz[np * 3 + 2];
        sOut[np * 132 + o] = sWgu[o * 6 + 3] * x0 + sWgu[o * 6 + 4] * x1 + sWgu[o * 6 + 5] * x2;
    }
    __syncthreads();
    for (int e = t * 4; e < 32 * 128; e += 512) {
        int np = e >> 7, f = e & 127;
        *(float4*)&g_nbr[(size_t)p0 * FD + e] = *(const float4*)&sOut[np * 132 + f];
    }
}

// ---------------------------------------------------------------------------
// Kernel 2 (main): persistent mma.sync bf16-split GEMM.
//   Per tile: M=128 (4 pts x 32 nbrs), K=128 (fuse), N=128 (DH).
//   D = Fh*Wh + Fl*Wh + Fh*Wl. Warp = (point w&3) x (N-half w>>2).
// smem rows padded to 272B: ldmatrix-conflict-free (272 mod 128 = 16).
// ---------------------------------------------------------------------------
#define RSB 272                      // row stride bytes (136 bf16)
#define RSW 68                       // row stride words
#define S_WH 0
#define S_WL 34816
#define S_AH 69632
#define S_AL 104448
#define S_IDX 139264                 // 128 ints
#define S_SH  139776                 // 128 floats
#define S_BH  140288                 // 128 floats
#define MAIN_SMEM 140800

__global__ void __launch_bounds__(256, 1) main_kernel(
    const int* __restrict__ idx,
    const float* __restrict__ s_gu, const float* __restrict__ b_gu,
    const float* __restrict__ s_gv, const float* __restrict__ b_gv,
    const float* __restrict__ W_h,
    const float* __restrict__ s_h, const float* __restrict__ b_h)
{
    extern __shared__ __align__(16) char smem[];
    uint32_t sbase = smem_u32(smem);
    uint32_t* sWh = (uint32_t*)(smem + S_WH);
    uint32_t* sWl = (uint32_t*)(smem + S_WL);
    uint32_t* sAh = (uint32_t*)(smem + S_AH);
    uint32_t* sAl = (uint32_t*)(smem + S_AL);
    int*   s_idx = (int*)(smem + S_IDX);
    float* s_sh  = (float*)(smem + S_SH);
    float* s_bh  = (float*)(smem + S_BH);

    int t = threadIdx.x;
    int lane = t & 31;
    int w = t >> 5;

    // gather-phase mapping: thread handles feature pair fp, point ptg
    int fp = t & 63;
    int ptg = t >> 6;

    if (t < 128) { s_sh[t] = s_h[t]; s_bh[t] = b_h[t]; }

    // fuse scale/bias for this feature pair
    int f0i = 2 * fp;
    float2 sv2, bv2;
    if (f0i < 64) {
        sv2 = *(const float2*)&s_gu[f0i];
        bv2 = *(const float2*)&b_gu[f0i];
    } else {
        sv2 = *(const float2*)&s_gv[f0i - 64];
        bv2 = *(const float2*)&b_gv[f0i - 64];
    }

    // W_h -> bf16 hi/lo, padded row-major [o][k]
#pragma unroll 8
    for (int ii = 0; ii < 32; ii++) {
        int o = ptg * 32 + ii;
        float2 wv = *(const float2*)&W_h[(size_t)o * 128 + 2 * fp];
        uint32_t hi, lo;
        split2(wv.x, wv.y, hi, lo);
        sWh[o * RSW + fp] = hi;
        sWl[o * RSW + fp] = lo;
    }

    // mma-phase mapping
    int pt_m = w & 3;
    int nh = w >> 2;

    // ldmatrix lane address bases
    uint32_t a_base[2];
#pragma unroll
    for (int mt = 0; mt < 2; mt++) {
        int arow = pt_m * 32 + mt * 16 + (lane & 15);
        a_base[mt] = sbase + S_AH + arow * RSB + ((lane >> 4) << 4);
    }
    uint32_t b_base[4];
#pragma unroll
    for (int ng = 0; ng < 4; ng++) {
        int brow = nh * 64 + ng * 16 + (lane & 7) + ((lane >> 4) << 3);
        b_base[ng] = sbase + S_WH + brow * RSB + (((lane >> 3) & 1) << 4);
    }

    for (int tile = blockIdx.x; tile < NTILES; tile += gridDim.x) {
        __syncthreads();   // protect s_idx / sA from previous iteration readers
        if (t < 128) {
            int pti = t >> 5, q = t & 31;
            int n = (tile * 4 + pti) & (NN - 1);
            s_idx[t] = idx[n * KK + q];
        }
        __syncthreads();

        // ---- gather + fuse + bf16 split into sAh/sAl ----
        {
            int p = tile * 4 + ptg;
            int b = p >> 12;
            float2 ctr2 = *(const float2*)&g_ctr[(size_t)p * FD + 2 * fp];
            const float* nbB = g_nbr + (size_t)b * NN * FD + 2 * fp;
#pragma unroll 8
            for (int q = 0; q < 32; q++) {
                int row = ptg * 32 + q;
                int j = s_idx[ptg * 32 + q];
                float2 v = *(const float2*)&nbB[(size_t)j * FD];
                float u0 = fmaxf((ctr2.x + v.x) * sv2.x + bv2.x, 0.f);
                float u1 = fmaxf((ctr2.y + v.y) * sv2.y + bv2.y, 0.f);
                uint32_t hi, lo;
                split2(u0, u1, hi, lo);
                sAh[row * RSW + fp] = hi;
                sAl[row * RSW + fp] = lo;
            }
        }
        __syncthreads();

        // ---- 32x64x128 sub-GEMM per warp, 3 bf16 terms ----
        float acc[2][8][4];
#pragma unroll
        for (int mt = 0; mt < 2; mt++)
#pragma unroll
            for (int j = 0; j < 8; j++)
#pragma unroll
                for (int r = 0; r < 4; r++) acc[mt][j][r] = 0.f;

#pragma unroll
        for (int ks = 0; ks < 8; ks++) {
            uint32_t koff = (uint32_t)ks * 32;   // 16 k-elems * 2B
            uint32_t ah[2][4], al[2][4], bh[4][4], bl[4][4];
#pragma unroll
            for (int mt = 0; mt < 2; mt++) {
                LDSM_X4(ah[mt][0], ah[mt][1], ah[mt][2], ah[mt][3], a_base[mt] + koff);
                LDSM_X4(al[mt][0], al[mt][1], al[mt][2], al[mt][3], a_base[mt] + 34816u + koff);
            }
#pragma unroll
            for (int ng = 0; ng < 4; ng++) {
                LDSM_X4(bh[ng][0], bh[ng][1], bh[ng][2], bh[ng][3], b_base[ng] + koff);
                LDSM_X4(bl[ng][0], bl[ng][1], bl[ng][2], bl[ng][3], b_base[ng] + 34816u + koff);
            }
#pragma unroll
            for (int mt = 0; mt < 2; mt++) {
#pragma unroll
                for (int ng = 0; ng < 4; ng++) {
                    // hi*hi
                    MMA_BF16(acc[mt][ng * 2 + 0], ah[mt], bh[ng][0], bh[ng][1]);
                    MMA_BF16(acc[mt][ng * 2 + 1], ah[mt], bh[ng][2], bh[ng][3]);
                    // lo*hi
                    MMA_BF16(acc[mt][ng * 2 + 0], al[mt], bh[ng][0], bh[ng][1]);
                    MMA_BF16(acc[mt][ng * 2 + 1], al[mt], bh[ng][2], bh[ng][3]);
                    // hi*lo
                    MMA_BF16(acc[mt][ng * 2 + 0], ah[mt], bl[ng][0], bl[ng][1]);
                    MMA_BF16(acc[mt][ng * 2 + 1], ah[mt], bl[ng][2], bl[ng][3]);
                }
            }
        }

        // ---- epilogue: relu(d*sh+bh), mean-pool over 32 rows, store ----
        {
            int p = tile * 4 + pt_m;
#pragma unroll
            for (int j = 0; j < 8; j++) {
                int col0 = nh * 64 + j * 8 + 2 * (lane & 3);
                float sc0 = s_sh[col0], sc1 = s_sh[col0 + 1];
                float bb0 = s_bh[col0], bb1 = s_bh[col0 + 1];
                float v0 = fmaxf(acc[0][j][0] * sc0 + bb0, 0.f)
                         + fmaxf(acc[0][j][2] * sc0 + bb0, 0.f)
                         + fmaxf(acc[1][j][0] * sc0 + bb0, 0.f)
                         + fmaxf(acc[1][j][2] * sc0 + bb0, 0.f);
                float v1 = fmaxf(acc[0][j][1] * sc1 + bb1, 0.f)
                         + fmaxf(acc[0][j][3] * sc1 + bb1, 0.f)
                         + fmaxf(acc[1][j][1] * sc1 + bb1, 0.f)
                         + fmaxf(acc[1][j][3] * sc1 + bb1, 0.f);
#pragma unroll
                for (int off = 4; off < 32; off <<= 1) {
                    v0 += __shfl_xor_sync(0xffffffffu, v0, off);
                    v1 += __shfl_xor_sync(0xffffffffu, v1, off);
                }
                if (lane < 4) {
                    *(float2*)&g_pooled[(size_t)p * DHH + nh * 64 + j * 8 + lane * 2] =
                        make_float2(v0 * (1.f / KK), v1 * (1.f / KK));
                }
            }
        }
    }
}

// ---------------------------------------------------------------------------
// Kernel 3: final MLP epilogue
// ---------------------------------------------------------------------------
#define EPI_SWF (128 * 68)
#define EPI_SPOOL (32 * 129)
#define EPI_SOUT (64 * 33)
#define EPI_SMEM_BYTES ((EPI_SWF + EPI_SPOOL + EPI_SOUT) * 4)

__global__ void __launch_bounds__(128) epilogue_kernel(
    const float* __restrict__ W_f,
    const float* __restrict__ s_f, const float* __restrict__ b_f,
    const float* __restrict__ features,
    float* __restrict__ out)
{
    extern __shared__ float sm[];
    float* sWf = sm;
    float* sPool = sWf + EPI_SWF;
    float* sOutE = sPool + EPI_SPOOL;

    int t = threadIdx.x;
    int p0 = blockIdx.x * 32;
    int b = p0 >> 12;
    int n0 = p0 & (NN - 1);

    for (int e = t; e < 64 * 128; e += 128) {
        int c = e >> 7, i = e & 127;
        sWf[i * 68 + c] = W_f[e];
    }
    for (int e = t; e < 32 * 128; e += 128) {
        int np = e >> 7, i = e & 127;
        sPool[np * 129 + i] = g_pooled[(size_t)p0 * DHH + e];
    }
    __syncthreads();

    {
        int np = t & 31;
        int c0 = (t >> 5) << 4;
        float acc[16];
#pragma unroll
        for (int j = 0; j < 16; j++) acc[j] = 0.f;
#pragma unroll 8
        for (int i = 0; i < 128; i++) {
            float a = sPool[np * 129 + i];
            const float4* wp = (const float4*)&sWf[i * 68 + c0];
#pragma unroll
            for (int v = 0; v < 4; v++) {
                float4 w = wp[v];
                acc[v * 4 + 0] += a * w.x;
                acc[v * 4 + 1] += a * w.y;
                acc[v * 4 + 2] += a * w.z;
                acc[v * 4 + 3] += a * w.w;
            }
        }
#pragma unroll
        for (int j = 0; j < 16; j++) {
            int c = c0 + j;
            sOutE[c * 33 + np] = fmaxf(acc[j] * __ldg(&s_f[c]) + __ldg(&b_f[c]), 0.f);
        }
    }
    __syncthreads();

    for (int e = t; e < 64 * 32; e += 128) {
        int c = e >> 5, np = e & 31;
        size_t o = (size_t)b * CC * NN + (size_t)c * NN + n0 + np;
        out[o] = sOutE[c * 33 + np] + features[o];
    }
}

// ---------------------------------------------------------------------------
extern "C" void kernel_launch(void* const* d_in, const int* in_sizes, int n_in,
                              void* d_out, int out_size)
{
    const float* xyz      = (const float*)d_in[0];
    const float* features = (const float*)d_in[1];
    const int*   idx      = (const int*)d_in[2];
    const float* W_gu     = (const float*)d_in[3];
    const float* s_gu     = (const float*)d_in[4];
    const float* b_gu     = (const float*)d_in[5];
    const float* W_gv     = (const float*)d_in[6];
    const float* s_gv     = (const float*)d_in[7];
    const float* b_gv     = (const float*)d_in[8];
    const float* W_h      = (const float*)d_in[9];
    const float* s_h      = (const float*)d_in[10];
    const float* b_h      = (const float*)d_in[11];
    const float* W_f      = (const float*)d_in[12];
    const float* s_f      = (const float*)d_in[13];
    const float* b_f      = (const float*)d_in[14];

    float* out = (float*)d_out;
    float* out_feat = out;
    const size_t xyz_elems = (size_t)BB * NN * 3;
    const size_t feat_elems = (size_t)BB * CC * NN;

    if ((size_t)out_size == xyz_elems + feat_elems) {
        cudaMemcpyAsync(out, xyz, xyz_elems * sizeof(float),
                        cudaMemcpyDeviceToDevice, 0);
        out_feat = out + xyz_elems;
    }

    cudaFuncSetAttribute(main_kernel,
                         cudaFuncAttributeMaxDynamicSharedMemorySize, MAIN_SMEM);
    cudaFuncSetAttribute(epilogue_kernel,
                         cudaFuncAttributeMaxDynamicSharedMemorySize, EPI_SMEM_BYTES);

    precompute_kernel<<<BN / 32, 128>>>(xyz, features, W_gu, W_gv);
    main_kernel<<<152, 256, MAIN_SMEM>>>(idx, s_gu, b_gu, s_gv, b_gv,
                                         W_h, s_h, b_h);
    epilogue_kernel<<<BN / 32, 128, EPI_SMEM_BYTES>>>(W_f, s_f, b_f, features,
                                                      out_feat);
}

// round 5
// speedup vs baseline: 4.2821x; 2.1582x over previous
#include <cuda_runtime.h>
#include <cuda_fp16.h>
#include <cstdint>

// Problem constants
#define BB 4
#define NN 4096
#define KK 32
#define CC 64
#define FD 128
#define DHH 128
#define BN (BB * NN)
#define NTILES (BN / 4)        // 4 points per tile (M = 4*32 = 128)

// Scratch (no cudaMalloc allowed)
__device__ float g_ctr[(size_t)BN * FD];
__device__ float g_nbr[(size_t)BN * FD];
__device__ float g_pooled[(size_t)BN * DHH];

// ---------------------------------------------------------------------------
// PTX helpers — baseline sm_80+ instructions only (compute_103-safe).
// ---------------------------------------------------------------------------
__device__ __forceinline__ uint32_t smem_u32(const void* p) {
    uint32_t a;
    asm("{ .reg .u64 t; cvta.to.shared.u64 t, %1; cvt.u32.u64 %0, t; }"
        : "=r"(a) : "l"(p));
    return a;
}

#define LDSM_X4(r0, r1, r2, r3, addr)                                        \
    asm volatile("ldmatrix.sync.aligned.m8n8.x4.shared.b16 {%0,%1,%2,%3}, [%4];" \
                 : "=r"(r0), "=r"(r1), "=r"(r2), "=r"(r3) : "r"(addr))

#define MMA_F16(d, a, b0, b1)                                                \
    asm volatile("mma.sync.aligned.m16n8k16.row.col.f32.f16.f16.f32 "        \
                 "{%0,%1,%2,%3}, {%4,%5,%6,%7}, {%8,%9}, {%0,%1,%2,%3};"     \
                 : "+f"((d)[0]), "+f"((d)[1]), "+f"((d)[2]), "+f"((d)[3])    \
                 : "r"((a)[0]), "r"((a)[1]), "r"((a)[2]), "r"((a)[3]),       \
                   "r"(b0), "r"(b1))

// fp16 hi/lo split of an fp32 pair -> two packed f16x2 words
__device__ __forceinline__ void splitf16(float f0, float f1, uint32_t& hi, uint32_t& lo) {
    __half2 h = __float22half2_rn(make_float2(f0, f1));
    float2 r = __half22float2(h);
    __half2 l = __float22half2_rn(make_float2(f0 - r.x, f1 - r.y));
    hi = *(uint32_t*)&h;
    lo = *(uint32_t*)&l;
}

// ---------------------------------------------------------------------------
// Kernel 1: precompute  g_ctr[p]=[U1;Gv], g_nbr[p]=[U2;Gv]
// ---------------------------------------------------------------------------
__global__ void __launch_bounds__(128) precompute_kernel(
    const float* __restrict__ xyz, const float* __restrict__ features,
    const float* __restrict__ W_gu, const float* __restrict__ W_gv)
{
    __shared__ float sWgv[64 * 64];
    __shared__ float sWgu[64 * 6];
    __shared__ float sF[64 * 33];
    __shared__ float sXyz[32 * 3];
    __shared__ float sOut[32 * 132];

    int t = threadIdx.x;
    int p0 = blockIdx.x * 32;
    int b = p0 >> 12;
    int n0 = p0 & (NN - 1);

    for (int e = t; e < 64 * 64; e += 128)
        sWgv[(e & 63) * 64 + (e >> 6)] = W_gv[e];
    for (int e = t; e < 64 * 6; e += 128)
        sWgu[e] = W_gu[e];
    for (int e = t; e < 64 * 32; e += 128) {
        int c = e >> 5, np = e & 31;
        sF[c * 33 + np] = features[(size_t)b * CC * NN + (size_t)c * NN + n0 + np];
    }
    for (int e = t; e < 96; e += 128)
        sXyz[e] = xyz[(size_t)p0 * 3 + e];
    __syncthreads();

    {
        int np = t & 31;
        int o0 = (t >> 5) << 4;
        float acc[16];
#pragma unroll
        for (int j = 0; j < 16; j++) acc[j] = 0.f;
#pragma unroll 8
        for (int c = 0; c < 64; c++) {
            float a = sF[c * 33 + np];
            const float4* wp = (const float4*)&sWgv[c * 64 + o0];
#pragma unroll
            for (int v = 0; v < 4; v++) {
                float4 w = wp[v];
                acc[v * 4 + 0] += a * w.x;
                acc[v * 4 + 1] += a * w.y;
                acc[v * 4 + 2] += a * w.z;
                acc[v * 4 + 3] += a * w.w;
            }
        }
#pragma unroll
        for (int j = 0; j < 16; j++)
            sOut[np * 132 + 64 + o0 + j] = acc[j];
    }
    for (int e = t; e < 32 * 64; e += 128) {
        int np = e >> 6, o = e & 63;
        float x0 = sXyz[np * 3], x1 = sXyz[np * 3 + 1], x2 = sXyz[np * 3 + 2];
        sOut[np * 132 + o] = sWgu[o * 6 + 0] * x0 + sWgu[o * 6 + 1] * x1 + sWgu[o * 6 + 2] * x2;
    }
    __syncthreads();
    for (int e = t * 4; e < 32 * 128; e += 512) {
        int np = e >> 7, f = e & 127;
        *(float4*)&g_ctr[(size_t)p0 * FD + e] = *(const float4*)&sOut[np * 132 + f];
    }
    __syncthreads();
    for (int e = t; e < 32 * 64; e += 128) {
        int np = e >> 6, o = e & 63;
        float x0 = sXyz[np * 3], x1 = sXyz[np * 3 + 1], x2 = sXyz[np * 3 + 2];
        sOut[np * 132 + o] = sWgu[o * 6 + 3] * x0 + sWgu[o * 6 + 4] * x1 + sWgu[o * 6 + 5] * x2;
    }
    __syncthreads();
    for (int e = t * 4; e < 32 * 128; e += 512) {
        int np = e >> 7, f = e & 127;
        *(float4*)&g_nbr[(size_t)p0 * FD + e] = *(const float4*)&sOut[np * 132 + f];
    }
}

// ---------------------------------------------------------------------------
// Kernel 2 (main): persistent mma.sync fp16 2-term GEMM, pipelined gather.
//   Per tile: M=128 (4 pts x 32 nbrs), K=128 (fuse), N=128 (DH).
//   D = Fh*Wh + Fl*Wh  (W in fp16, F split hi/lo in fp16)
// 512 threads / 16 warps: warp = (point w&3) x (N-quarter w>>2).
// smem rows padded to 272B -> ldmatrix conflict-free.
// ---------------------------------------------------------------------------
#define RSB 272                      // row stride bytes (136 halves... 128 data + pad)
#define RSW 68                       // row stride in 32-bit words
#define S_WH 0                       // W fp16        34816 B
#define S_AH 34816                   // A hi          34816 B
#define S_AL 69632                   // A lo          34816 B
#define S_IDX 104448                 // 2 x 128 ints  1024 B
#define S_SH  105472                 // 128 floats
#define S_BH  105984                 // 128 floats
#define MAIN_SMEM 106496

__global__ void __launch_bounds__(512, 1) main_kernel(
    const int* __restrict__ idx,
    const float* __restrict__ s_gu, const float* __restrict__ b_gu,
    const float* __restrict__ s_gv, const float* __restrict__ b_gv,
    const float* __restrict__ W_h,
    const float* __restrict__ s_h, const float* __restrict__ b_h)
{
    extern __shared__ __align__(16) char smem[];
    uint32_t sbase = smem_u32(smem);
    uint32_t* sWh = (uint32_t*)(smem + S_WH);
    uint32_t* sAh = (uint32_t*)(smem + S_AH);
    uint32_t* sAl = (uint32_t*)(smem + S_AL);
    int*   s_idx = (int*)(smem + S_IDX);      // double-buffered 2x128
    float* s_sh  = (float*)(smem + S_SH);
    float* s_bh  = (float*)(smem + S_BH);

    int t = threadIdx.x;
    int lane = t & 31;
    int w = t >> 5;

    // gather mapping: feature pair fp, point ptg, q-half qh
    int fp = t & 63;
    int ptg = (t >> 6) & 3;
    int qh = t >> 8;            // 0/1 -> q in [qh*16, qh*16+16)

    if (t < 128) { s_sh[t] = s_h[t]; s_bh[t] = b_h[t]; }

    // fuse scale/bias for this feature pair
    int f0i = 2 * fp;
    float2 sv2, bv2;
    if (f0i < 64) {
        sv2 = *(const float2*)&s_gu[f0i];
        bv2 = *(const float2*)&b_gu[f0i];
    } else {
        sv2 = *(const float2*)&s_gv[f0i - 64];
        bv2 = *(const float2*)&b_gv[f0i - 64];
    }

    // W_h -> fp16, padded row-major [o][k]
    {
        int og = t >> 6;        // 0..7, 16 rows each
#pragma unroll
        for (int ii = 0; ii < 16; ii++) {
            int o = og * 16 + ii;
            float2 wv = *(const float2*)&W_h[(size_t)o * 128 + 2 * fp];
            __half2 h = __float22half2_rn(make_float2(wv.x, wv.y));
            sWh[o * RSW + fp] = *(uint32_t*)&h;
        }
    }

    // mma mapping: pt_m = point, nq = N-quarter (32 cols)
    int pt_m = w & 3;
    int nq = w >> 2;

    uint32_t a_base[2];
#pragma unroll
    for (int mt = 0; mt < 2; mt++) {
        int arow = pt_m * 32 + mt * 16 + (lane & 15);
        a_base[mt] = sbase + S_AH + arow * RSB + ((lane >> 4) << 4);
    }
    uint32_t b_base[2];
#pragma unroll
    for (int g = 0; g < 2; g++) {
        int brow = nq * 32 + g * 16 + (lane & 7) + ((lane >> 4) << 3);
        b_base[g] = sbase + S_WH + brow * RSB + (((lane >> 3) & 1) << 4);
    }

    const int grid = gridDim.x;

    // ---- prologue: idx(tile0) -> buf0, prefetch gather(tile0), idx(tile1) -> buf1
    int tile = blockIdx.x;
    float2 vreg[16];
    float2 ctr2;
    if (t < 128 && tile < NTILES) {
        int n = (tile * 4 + (t >> 5)) & (NN - 1);
        s_idx[t] = idx[n * KK + (t & 31)];
    }
    __syncthreads();
    if (tile < NTILES) {
        int p = tile * 4 + ptg;
        int b = p >> 12;
        ctr2 = *(const float2*)&g_ctr[(size_t)p * FD + 2 * fp];
        const float* nbB = g_nbr + (size_t)b * NN * FD + 2 * fp;
        const int* si = s_idx + ptg * 32 + qh * 16;
#pragma unroll
        for (int q = 0; q < 16; q++) {
            int j = si[q];
            vreg[q] = *(const float2*)&nbB[(size_t)j * FD];
        }
    }
    {
        int nt1 = tile + grid;
        if (t < 128 && nt1 < NTILES) {
            int n = (nt1 * 4 + (t >> 5)) & (NN - 1);
            s_idx[128 + t] = idx[n * KK + (t & 31)];
        }
    }

    int it = 0;
    for (; tile < NTILES; tile += grid, it ^= 1) {
        __syncthreads();   // A buffer free (prev MMA done) + s_idx stores visible

        // ---- STS phase: fuse + fp16 split of current tile (from registers) ----
        {
            int rowb = ptg * 32 + qh * 16;
#pragma unroll
            for (int q = 0; q < 16; q++) {
                float u0 = fmaxf((ctr2.x + vreg[q].x) * sv2.x + bv2.x, 0.f);
                float u1 = fmaxf((ctr2.y + vreg[q].y) * sv2.y + bv2.y, 0.f);
                uint32_t hi, lo;
                splitf16(u0, u1, hi, lo);
                sAh[(rowb + q) * RSW + fp] = hi;
                sAl[(rowb + q) * RSW + fp] = lo;
            }
        }
        __syncthreads();

        // ---- prefetch gather for next tile (hides L2 latency under MMA) ----
        int nt = tile + grid;
        float2 ctr_next;
        if (nt < NTILES) {
            int p = nt * 4 + ptg;
            int b = p >> 12;
            ctr_next = *(const float2*)&g_ctr[(size_t)p * FD + 2 * fp];
            const float* nbB = g_nbr + (size_t)b * NN * FD + 2 * fp;
            const int* si = s_idx + (it ^ 1) * 128 + ptg * 32 + qh * 16;
#pragma unroll
            for (int q = 0; q < 16; q++) {
                int j = si[q];
                vreg[q] = *(const float2*)&nbB[(size_t)j * FD];
            }
        }
        int nt2 = tile + 2 * grid;
        if (t < 128 && nt2 < NTILES) {
            int n = (nt2 * 4 + (t >> 5)) & (NN - 1);
            s_idx[it * 128 + t] = idx[n * KK + (t & 31)];
        }

        // ---- MMA: 32x32x128 per warp, 2 fp16 terms ----
        float acc[2][4][4];
#pragma unroll
        for (int mt = 0; mt < 2; mt++)
#pragma unroll
            for (int j = 0; j < 4; j++)
#pragma unroll
                for (int r = 0; r < 4; r++) acc[mt][j][r] = 0.f;

#pragma unroll
        for (int ks = 0; ks < 8; ks++) {
            uint32_t koff = (uint32_t)ks * 32;
            uint32_t ah[2][4], al[2][4], bf[2][4];
#pragma unroll
            for (int mt = 0; mt < 2; mt++) {
                LDSM_X4(ah[mt][0], ah[mt][1], ah[mt][2], ah[mt][3], a_base[mt] + koff);
                LDSM_X4(al[mt][0], al[mt][1], al[mt][2], al[mt][3], a_base[mt] + 34816u + koff);
            }
#pragma unroll
            for (int g = 0; g < 2; g++)
                LDSM_X4(bf[g][0], bf[g][1], bf[g][2], bf[g][3], b_base[g] + koff);

            // term 1: Ah * W  (8 distinct accumulators before reuse)
#pragma unroll
            for (int mt = 0; mt < 2; mt++)
#pragma unroll
                for (int g = 0; g < 2; g++) {
                    MMA_F16(acc[mt][g * 2 + 0], ah[mt], bf[g][0], bf[g][1]);
                    MMA_F16(acc[mt][g * 2 + 1], ah[mt], bf[g][2], bf[g][3]);
                }
            // term 2: Al * W
#pragma unroll
            for (int mt = 0; mt < 2; mt++)
#pragma unroll
                for (int g = 0; g < 2; g++) {
                    MMA_F16(acc[mt][g * 2 + 0], al[mt], bf[g][0], bf[g][1]);
                    MMA_F16(acc[mt][g * 2 + 1], al[mt], bf[g][2], bf[g][3]);
                }
        }

        // ---- epilogue: relu(d*sh+bh), mean-pool over 32 rows, store ----
        {
            int p = tile * 4 + pt_m;
#pragma unroll
            for (int j = 0; j < 4; j++) {
                int col0 = nq * 32 + j * 8 + 2 * (lane & 3);
                float sc0 = s_sh[col0], sc1 = s_sh[col0 + 1];
                float bb0 = s_bh[col0], bb1 = s_bh[col0 + 1];
                float v0 = fmaxf(acc[0][j][0] * sc0 + bb0, 0.f)
                         + fmaxf(acc[0][j][2] * sc0 + bb0, 0.f)
                         + fmaxf(acc[1][j][0] * sc0 + bb0, 0.f)
                         + fmaxf(acc[1][j][2] * sc0 + bb0, 0.f);
                float v1 = fmaxf(acc[0][j][1] * sc1 + bb1, 0.f)
                         + fmaxf(acc[0][j][3] * sc1 + bb1, 0.f)
                         + fmaxf(acc[1][j][1] * sc1 + bb1, 0.f)
                         + fmaxf(acc[1][j][3] * sc1 + bb1, 0.f);
#pragma unroll
                for (int off = 4; off < 32; off <<= 1) {
                    v0 += __shfl_xor_sync(0xffffffffu, v0, off);
                    v1 += __shfl_xor_sync(0xffffffffu, v1, off);
                }
                if (lane < 4) {
                    *(float2*)&g_pooled[(size_t)p * DHH + nq * 32 + j * 8 + lane * 2] =
                        make_float2(v0 * (1.f / KK), v1 * (1.f / KK));
                }
            }
        }
        ctr2 = ctr_next;
    }
}

// ---------------------------------------------------------------------------
// Kernel 3: final MLP epilogue
// ---------------------------------------------------------------------------
#define EPI_SWF (128 * 68)
#define EPI_SPOOL (32 * 129)
#define EPI_SOUT (64 * 33)
#define EPI_SMEM_BYTES ((EPI_SWF + EPI_SPOOL + EPI_SOUT) * 4)

__global__ void __launch_bounds__(128) epilogue_kernel(
    const float* __restrict__ W_f,
    const float* __restrict__ s_f, const float* __restrict__ b_f,
    const float* __restrict__ features,
    float* __restrict__ out)
{
    extern __shared__ float sm[];
    float* sWf = sm;
    float* sPool = sWf + EPI_SWF;
    float* sOutE = sPool + EPI_SPOOL;

    int t = threadIdx.x;
    int p0 = blockIdx.x * 32;
    int b = p0 >> 12;
    int n0 = p0 & (NN - 1);

    for (int e = t; e < 64 * 128; e += 128) {
        int c = e >> 7, i = e & 127;
        sWf[i * 68 + c] = W_f[e];
    }
    for (int e = t; e < 32 * 128; e += 128) {
        int np = e >> 7, i = e & 127;
        sPool[np * 129 + i] = g_pooled[(size_t)p0 * DHH + e];
    }
    __syncthreads();

    {
        int np = t & 31;
        int c0 = (t >> 5) << 4;
        float acc[16];
#pragma unroll
        for (int j = 0; j < 16; j++) acc[j] = 0.f;
#pragma unroll 8
        for (int i = 0; i < 128; i++) {
            float a = sPool[np * 129 + i];
            const float4* wp = (const float4*)&sWf[i * 68 + c0];
#pragma unroll
            for (int v = 0; v < 4; v++) {
                float4 w = wp[v];
                acc[v * 4 + 0] += a * w.x;
                acc[v * 4 + 1] += a * w.y;
                acc[v * 4 + 2] += a * w.z;
                acc[v * 4 + 3] += a * w.w;
            }
        }
#pragma unroll
        for (int j = 0; j < 16; j++) {
            int c = c0 + j;
            sOutE[c * 33 + np] = fmaxf(acc[j] * __ldg(&s_f[c]) + __ldg(&b_f[c]), 0.f);
        }
    }
    __syncthreads();

    for (int e = t; e < 64 * 32; e += 128) {
        int c = e >> 5, np = e & 31;
        size_t o = (size_t)b * CC * NN + (size_t)c * NN + n0 + np;
        out[o] = sOutE[c * 33 + np] + features[o];
    }
}

// ---------------------------------------------------------------------------
extern "C" void kernel_launch(void* const* d_in, const int* in_sizes, int n_in,
                              void* d_out, int out_size)
{
    const float* xyz      = (const float*)d_in[0];
    const float* features = (const float*)d_in[1];
    const int*   idx      = (const int*)d_in[2];
    const float* W_gu     = (const float*)d_in[3];
    const float* s_gu     = (const float*)d_in[4];
    const float* b_gu     = (const float*)d_in[5];
    const float* W_gv     = (const float*)d_in[6];
    const float* s_gv     = (const float*)d_in[7];
    const float* b_gv     = (const float*)d_in[8];
    const float* W_h      = (const float*)d_in[9];
    const float* s_h      = (const float*)d_in[10];
    const float* b_h      = (const float*)d_in[11];
    const float* W_f      = (const float*)d_in[12];
    const float* s_f      = (const float*)d_in[13];
    const float* b_f      = (const float*)d_in[14];

    float* out = (float*)d_out;
    float* out_feat = out;
    const size_t xyz_elems = (size_t)BB * NN * 3;
    const size_t feat_elems = (size_t)BB * CC * NN;

    if ((size_t)out_size == xyz_elems + feat_elems) {
        cudaMemcpyAsync(out, xyz, xyz_elems * sizeof(float),
                        cudaMemcpyDeviceToDevice, 0);
        out_feat = out + xyz_elems;
    }

    cudaFuncSetAttribute(main_kernel,
                         cudaFuncAttributeMaxDynamicSharedMemorySize, MAIN_SMEM);
    cudaFuncSetAttribute(epilogue_kernel,
                         cudaFuncAttributeMaxDynamicSharedMemorySize, EPI_SMEM_BYTES);

    precompute_kernel<<<BN / 32, 128>>>(xyz, features, W_gu, W_gv);
    main_kernel<<<152, 512, MAIN_SMEM>>>(idx, s_gu, b_gu, s_gv, b_gv,
                                         W_h, s_h, b_h);
    epilogue_kernel<<<BN / 32, 128, EPI_SMEM_BYTES>>>(W_f, s_f, b_f, features,
                                                      out_feat);
}